// round 13
// baseline (speedup 1.0000x reference)
#include <cuda_runtime.h>
#include <cuda_fp16.h>

#define H 64
#define IN_DIM 16
#define NMAX 50048
#define EPADMAX 1200000
#define SHS 72  // padded smem row stride in halves (144 B)

// scratch (allocation-free rule: __device__ globals)
__device__ float    g_dinv[NMAX];
__device__ float    g_h[NMAX * H];          // h fp32 (residual; node-local read/write)
__device__ __half   g_hh[2 * NMAX * H];     // h fp16, double-buffered (neighbor gathers)
__device__ __half   g_wh[3 * H * H];        // W_conv transposed fp16: [l][n][k]
__device__ int      g_cnt[NMAX];
__device__ int      g_rowptr[NMAX + 1];
__device__ int      g_wr[NMAX];
__device__ __align__(16) unsigned g_se[EPADMAX];  // {norm:f16 <<16 | src:u16}; rows padded to 8
__device__ int      g_bsum[64];

// ---------------- W pre-convert ----------------

__global__ void convW(const float* __restrict__ W) {
    int i = blockIdx.x * blockDim.x + threadIdx.x;
    if (i >= 3 * H * H) return;
    int l = i >> 12, rem = i & 4095, n = rem >> 6, k = rem & 63;
    g_wh[i] = __float2half_rn(W[l * H * H + k * H + n]);
}

// ---------------- CSR build ----------------

__global__ void count_kernel(const int* __restrict__ col, int E) {
    int e = blockIdx.x * blockDim.x + threadIdx.x;
    if (e < E) atomicAdd(&g_cnt[col[e]], 1);
}

__global__ void scanA(int N) {
    __shared__ int wsum[32];
    __shared__ int wpre[32];
    int tid = threadIdx.x, lane = tid & 31, w = tid >> 5;
    int i = blockIdx.x * 1024 + tid;
    int v = (i < N) ? ((g_cnt[i] + 7) & ~7) : 0;
    int x = v;
#pragma unroll
    for (int o = 1; o < 32; o <<= 1) {
        int t = __shfl_up_sync(0xFFFFFFFFu, x, o);
        if (lane >= o) x += t;
    }
    if (lane == 31) wsum[w] = x;
    __syncthreads();
    if (w == 0) {
        int y = wsum[lane];
#pragma unroll
        for (int o = 1; o < 32; o <<= 1) {
            int t = __shfl_up_sync(0xFFFFFFFFu, y, o);
            if (lane >= o) y += t;
        }
        wpre[lane] = y - wsum[lane];
        if (lane == 31) g_bsum[blockIdx.x] = y;
    }
    __syncthreads();
    if (i < N) g_rowptr[i] = wpre[w] + x - v;
}

__global__ void scanC(int N) {
    __shared__ int sbase;
    int i = blockIdx.x * 256 + threadIdx.x;
    int seg = (blockIdx.x * 256) >> 10;
    if (threadIdx.x < 32) {
        int l = threadIdx.x;
        int v = ((l < seg) ? g_bsum[l] : 0) + ((l + 32 < seg) ? g_bsum[l + 32] : 0);
#pragma unroll
        for (int o = 16; o; o >>= 1) v += __shfl_xor_sync(0xFFFFFFFFu, v, o);
        if (l == 0) sbase = v;
    }
    __syncthreads();
    if (i < N) {
        int rp = g_rowptr[i] + sbase;
        g_rowptr[i] = rp;
        g_wr[i] = rp;
        g_dinv[i] = rsqrtf((float)g_cnt[i] + 1.0f);
        if (i == N - 1) g_rowptr[N] = rp + ((g_cnt[i] + 7) & ~7);
    }
}

__global__ void build_kernel(const int* __restrict__ ei, int E) {
    int e = blockIdx.x * blockDim.x + threadIdx.x;
    if (e >= E) return;
    int r = ei[e], c = ei[E + e];
    int slot = atomicAdd(&g_wr[c], 1);
    __half nh = __float2half_rn(g_dinv[r] * g_dinv[c]);
    g_se[slot] = ((unsigned)__half_as_ushort(nh) << 16) | (unsigned)r;
}

// ---------------- input GEMM: h = relu(x @ W_in + b_in); writes fp32 + fp16(buf0) --------

__global__ void __launch_bounds__(256) in_gemm(const float* __restrict__ x,
                                               const float* __restrict__ Win,
                                               const float* __restrict__ bin, int N) {
    __shared__ __align__(16) float sx[64][IN_DIM];
    int tid = threadIdx.x;
    int j = tid & 63, sub = tid >> 6;
    int base = blockIdx.x * 64;
    int nn = N - base;
    if (nn > 64) nn = 64;
    if (nn <= 0) return;

    float w[IN_DIM];
#pragma unroll
    for (int k = 0; k < IN_DIM; k++) w[k] = Win[k * H + j];
    float bj = bin[j];

    const float4* xsrc = (const float4*)&x[base * IN_DIM];
    float4* sdst = (float4*)sx;
    int nvec = nn * (IN_DIM / 4);
    for (int i = tid; i < nvec; i += 256) sdst[i] = xsrc[i];
    __syncthreads();

    for (int n = sub; n < nn; n += 4) {
        const float4* sp = (const float4*)&sx[n][0];
        float4 s0 = sp[0], s1 = sp[1], s2 = sp[2], s3 = sp[3];
        float acc = bj;
        acc += s0.x * w[0]  + s0.y * w[1]  + s0.z * w[2]  + s0.w * w[3];
        acc += s1.x * w[4]  + s1.y * w[5]  + s1.z * w[6]  + s1.w * w[7];
        acc += s2.x * w[8]  + s2.y * w[9]  + s2.z * w[10] + s2.w * w[11];
        acc += s3.x * w[12] + s3.y * w[13] + s3.z * w[14] + s3.w * w[15];
        acc = fmaxf(acc, 0.0f);
        g_h[(base + n) * H + j] = acc;
        g_hh[(base + n) * H + j] = __float2half_rn(acc);
    }
}

// ---------------- fused layer: gather(h) -> mma(@W) -> bias+LN+ReLU+residual(+head) ------
// block = 256 thr (8 warps) x 128 nodes. warp w owns rows w*16..+15 end-to-end:
// gathers them (lane = 2 features), feeds its own ldmatrix A-tile, LN's its own D rows.

__device__ __forceinline__ void unpack_se(unsigned m, int& src, float& nm) {
    src = (int)(m & 0xFFFFu);
    nm = __half2float(__ushort_as_half((unsigned short)(m >> 16)));
}

__global__ void __launch_bounds__(256) layer_fused(int layer, int rdbuf, int wrbuf,
        const float* __restrict__ b, const float* __restrict__ gamma,
        const float* __restrict__ beta, const float* __restrict__ Wout,
        const float* __restrict__ bout, float* __restrict__ out, int N, int last) {
    __shared__ __half sH[128 * SHS];
    __shared__ __half sWT[64 * SHS];
    int tid = threadIdx.x;
    int base = blockIdx.x * 128;

    // W tile (fp16, pre-transposed)
    {
        const uint4* wsrc = (const uint4*)&g_wh[layer * H * H];
        for (int i = tid; i < 512; i += 256) {
            int row = i >> 3, q = i & 7;
            *(uint4*)&sWT[row * SHS + q * 8] = wsrc[row * 8 + q];
        }
    }
    __syncthreads();  // the only block-wide sync

    int w = tid >> 5, lane = tid & 31;
    int m0 = w * 16;
    const __half2* t2 = (const __half2*)&g_hh[rdbuf * NMAX * H];

    // ---- gather phase: pre_agg = d^2*h[node] + sum norm*h[src]  (fp32 accum, fp16 out) ----
    for (int i = 0; i < 16; i++) {
        int node = base + m0 + i;
        float accx = 0.0f, accy = 0.0f;
        if (node < N) {
            float d = g_dinv[node];
            float2 tn = __half22float2(t2[node * 32 + lane]);
            accx = tn.x * d * d;
            accy = tn.y * d * d;
            int s = g_rowptr[node], e = g_rowptr[node + 1];
            for (int j = s; j < e; j += 8) {
                const uint4* mp = (const uint4*)&g_se[j];
                uint4 ma = mp[0], mb = mp[1];
                int r0, r1, r2, r3, r4, r5, r6, r7;
                float n0, n1, n2, n3, n4, n5, n6, n7;
                unpack_se(ma.x, r0, n0); unpack_se(ma.y, r1, n1);
                unpack_se(ma.z, r2, n2); unpack_se(ma.w, r3, n3);
                unpack_se(mb.x, r4, n4); unpack_se(mb.y, r5, n5);
                unpack_se(mb.z, r6, n6); unpack_se(mb.w, r7, n7);
                float2 v0 = __half22float2(t2[r0 * 32 + lane]);
                float2 v1 = __half22float2(t2[r1 * 32 + lane]);
                float2 v2 = __half22float2(t2[r2 * 32 + lane]);
                float2 v3 = __half22float2(t2[r3 * 32 + lane]);
                float2 v4 = __half22float2(t2[r4 * 32 + lane]);
                float2 v5 = __half22float2(t2[r5 * 32 + lane]);
                float2 v6 = __half22float2(t2[r6 * 32 + lane]);
                float2 v7 = __half22float2(t2[r7 * 32 + lane]);
                accx += v0.x * n0 + v1.x * n1 + v2.x * n2 + v3.x * n3
                      + v4.x * n4 + v5.x * n5 + v6.x * n6 + v7.x * n7;
                accy += v0.y * n0 + v1.y * n1 + v2.y * n2 + v3.y * n3
                      + v4.y * n4 + v5.y * n5 + v6.y * n6 + v7.y * n7;
            }
        }
        ((__half2*)&sH[(m0 + i) * SHS])[lane] = __floats2half2_rn(accx, accy);
    }
    __syncwarp();  // A-tile rows are warp-private

    // ---- mma: agg_pre @ W ----
    float acc[8][4];
#pragma unroll
    for (int nt = 0; nt < 8; nt++)
#pragma unroll
        for (int q = 0; q < 4; q++) acc[nt][q] = 0.0f;

    unsigned a_base = (unsigned)__cvta_generic_to_shared(
        &sH[(m0 + (lane & 15)) * SHS + ((lane >> 4) & 1) * 8]);
    int bm = lane >> 3, brow = lane & 7;

#pragma unroll
    for (int kk = 0; kk < 64; kk += 16) {
        unsigned a0, a1, a2, a3;
        asm volatile("ldmatrix.sync.aligned.m8n8.x4.shared.b16 {%0,%1,%2,%3}, [%4];"
                     : "=r"(a0), "=r"(a1), "=r"(a2), "=r"(a3)
                     : "r"(a_base + kk * 2));
#pragma unroll
        for (int g = 0; g < 4; g++) {
            unsigned b_addr = (unsigned)__cvta_generic_to_shared(
                &sWT[((2 * g + (bm >> 1)) * 8 + brow) * SHS + kk + (bm & 1) * 8]);
            unsigned b0, b1, b2, b3;
            asm volatile("ldmatrix.sync.aligned.m8n8.x4.shared.b16 {%0,%1,%2,%3}, [%4];"
                         : "=r"(b0), "=r"(b1), "=r"(b2), "=r"(b3) : "r"(b_addr));
            int t0 = 2 * g, t1 = 2 * g + 1;
            asm volatile("mma.sync.aligned.m16n8k16.row.col.f32.f16.f16.f32 "
                         "{%0,%1,%2,%3}, {%4,%5,%6,%7}, {%8,%9}, {%0,%1,%2,%3};"
                         : "+f"(acc[t0][0]), "+f"(acc[t0][1]), "+f"(acc[t0][2]), "+f"(acc[t0][3])
                         : "r"(a0), "r"(a1), "r"(a2), "r"(a3), "r"(b0), "r"(b1));
            asm volatile("mma.sync.aligned.m16n8k16.row.col.f32.f16.f16.f32 "
                         "{%0,%1,%2,%3}, {%4,%5,%6,%7}, {%8,%9}, {%0,%1,%2,%3};"
                         : "+f"(acc[t1][0]), "+f"(acc[t1][1]), "+f"(acc[t1][2]), "+f"(acc[t1][3])
                         : "r"(a0), "r"(a1), "r"(a2), "r"(a3), "r"(b2), "r"(b3));
        }
    }

    // ---- epilogue: bias, LN (4-lane reduce), relu, residual, store, head ----
    int gq = lane & 3;               // column quad
    int r0 = base + m0 + (lane >> 2);
    int r1 = r0 + 8;

    float2 bc[8], gc[8], bec[8];
#pragma unroll
    for (int nt = 0; nt < 8; nt++) {
        int c = nt * 8 + gq * 2;
        bc[nt] = *(const float2*)&b[c];
        gc[nt] = *(const float2*)&gamma[c];
        bec[nt] = *(const float2*)&beta[c];
        acc[nt][0] += bc[nt].x; acc[nt][1] += bc[nt].y;  // rows r0
        acc[nt][2] += bc[nt].x; acc[nt][3] += bc[nt].y;  // rows r1
    }

    float s0 = 0.0f, s1 = 0.0f;
#pragma unroll
    for (int nt = 0; nt < 8; nt++) {
        s0 += acc[nt][0] + acc[nt][1];
        s1 += acc[nt][2] + acc[nt][3];
    }
    s0 += __shfl_xor_sync(0xFFFFFFFFu, s0, 1); s0 += __shfl_xor_sync(0xFFFFFFFFu, s0, 2);
    s1 += __shfl_xor_sync(0xFFFFFFFFu, s1, 1); s1 += __shfl_xor_sync(0xFFFFFFFFu, s1, 2);
    float mu0 = s0 * (1.0f / 64.0f), mu1 = s1 * (1.0f / 64.0f);

    float v0 = 0.0f, v1 = 0.0f;
#pragma unroll
    for (int nt = 0; nt < 8; nt++) {
        float d0 = acc[nt][0] - mu0, d1 = acc[nt][1] - mu0;
        float d2 = acc[nt][2] - mu1, d3 = acc[nt][3] - mu1;
        v0 += d0 * d0 + d1 * d1;
        v1 += d2 * d2 + d3 * d3;
    }
    v0 += __shfl_xor_sync(0xFFFFFFFFu, v0, 1); v0 += __shfl_xor_sync(0xFFFFFFFFu, v0, 2);
    v1 += __shfl_xor_sync(0xFFFFFFFFu, v1, 1); v1 += __shfl_xor_sync(0xFFFFFFFFu, v1, 2);
    float inv0 = rsqrtf(v0 * (1.0f / 64.0f) + 1e-5f);
    float inv1 = rsqrtf(v1 * (1.0f / 64.0f) + 1e-5f);

    __half* hhw = &g_hh[wrbuf * NMAX * H];
    float o0 = 0.0f, o1 = 0.0f;
#pragma unroll
    for (int nt = 0; nt < 8; nt++) {
        int c = nt * 8 + gq * 2;
        if (r0 < N) {
            float2 hres = *(float2*)&g_h[r0 * H + c];
            float y0 = fmaxf((acc[nt][0] - mu0) * inv0 * gc[nt].x + bec[nt].x, 0.0f) + hres.x;
            float y1 = fmaxf((acc[nt][1] - mu0) * inv0 * gc[nt].y + bec[nt].y, 0.0f) + hres.y;
            if (last) {
                float2 wo = *(const float2*)&Wout[c];
                o0 += y0 * wo.x + y1 * wo.y;
            } else {
                *(float2*)&g_h[r0 * H + c] = make_float2(y0, y1);
                *(__half2*)&hhw[r0 * H + c] = __floats2half2_rn(y0, y1);
            }
        }
        if (r1 < N) {
            float2 hres = *(float2*)&g_h[r1 * H + c];
            float y2 = fmaxf((acc[nt][2] - mu1) * inv1 * gc[nt].x + bec[nt].x, 0.0f) + hres.x;
            float y3 = fmaxf((acc[nt][3] - mu1) * inv1 * gc[nt].y + bec[nt].y, 0.0f) + hres.y;
            if (last) {
                float2 wo = *(const float2*)&Wout[c];
                o1 += y2 * wo.x + y3 * wo.y;
            } else {
                *(float2*)&g_h[r1 * H + c] = make_float2(y2, y3);
                *(__half2*)&hhw[r1 * H + c] = __floats2half2_rn(y2, y3);
            }
        }
    }
    if (last) {
        o0 += __shfl_xor_sync(0xFFFFFFFFu, o0, 1); o0 += __shfl_xor_sync(0xFFFFFFFFu, o0, 2);
        o1 += __shfl_xor_sync(0xFFFFFFFFu, o1, 1); o1 += __shfl_xor_sync(0xFFFFFFFFu, o1, 2);
        if (gq == 0) {
            float bo = bout[0];
            if (r0 < N) out[r0] = o0 + bo;
            if (r1 < N) out[r1] = o1 + bo;
        }
    }
}

// ---------------- launch ----------------

extern "C" void kernel_launch(void* const* d_in, const int* in_sizes, int n_in,
                              void* d_out, int out_size) {
    const float* x      = (const float*)d_in[0];
    const int*   ei     = (const int*)d_in[1];
    const float* W_in   = (const float*)d_in[2];
    const float* b_in   = (const float*)d_in[3];
    const float* W_conv = (const float*)d_in[4];
    const float* b_conv = (const float*)d_in[5];
    const float* gamma  = (const float*)d_in[6];
    const float* beta   = (const float*)d_in[7];
    const float* W_out  = (const float*)d_in[8];
    const float* b_out  = (const float*)d_in[9];
    float* out = (float*)d_out;

    int N = in_sizes[0] / IN_DIM;
    int E = in_sizes[1] / 2;
    int nblk_scan = (N + 1023) / 1024;

    cudaStream_t s2;
    cudaStreamCreate(&s2);
    cudaEvent_t e0, e1;
    cudaEventCreate(&e0);
    cudaEventCreate(&e1);

    // branch A part 1: CSR counts
    void* cnt_ptr = nullptr; void* se_ptr = nullptr;
    cudaGetSymbolAddress(&cnt_ptr, g_cnt);
    cudaGetSymbolAddress(&se_ptr, g_se);
    cudaMemsetAsync(cnt_ptr, 0, (size_t)N * sizeof(int));
    size_t se_bytes = (size_t)E * sizeof(unsigned) + (size_t)N * 8 * sizeof(unsigned);
    if (se_bytes > (size_t)EPADMAX * sizeof(unsigned)) se_bytes = (size_t)EPADMAX * sizeof(unsigned);
    cudaMemsetAsync(se_ptr, 0, se_bytes);
    count_kernel<<<(E + 255) / 256, 256>>>(ei + E, E);
    scanA<<<nblk_scan, 1024>>>(N);

    // fork branch B (independent): W convert + input GEMM
    cudaEventRecord(e0, 0);
    cudaStreamWaitEvent(s2, e0, 0);
    convW<<<48, 256, 0, s2>>>(W_conv);
    in_gemm<<<(N + 63) / 64, 256, 0, s2>>>(x, W_in, b_in, N);
    cudaEventRecord(e1, s2);

    // branch A part 2
    scanC<<<(N + 255) / 256, 256>>>(N);
    build_kernel<<<(E + 255) / 256, 256>>>(ei, E);

    // join
    cudaStreamWaitEvent(0, e1, 0);

    int nblk = (N + 127) / 128;
    layer_fused<<<nblk, 256>>>(0, 0, 1, b_conv,         gamma,         beta,
                               W_out, b_out, out, N, 0);
    layer_fused<<<nblk, 256>>>(1, 1, 0, b_conv + H,     gamma + H,     beta + H,
                               W_out, b_out, out, N, 0);
    layer_fused<<<nblk, 256>>>(2, 0, 1, b_conv + 2 * H, gamma + 2 * H, beta + 2 * H,
                               W_out, b_out, out, N, 1);

    cudaEventDestroy(e0);
    cudaEventDestroy(e1);
    cudaStreamDestroy(s2);
}

// round 15
// speedup vs baseline: 1.2157x; 1.2157x over previous
#include <cuda_runtime.h>
#include <cuda_fp16.h>

#define H 64
#define IN_DIM 16
#define NMAX 50048
#define EPADMAX 1200000
#define SHS 72  // padded smem row stride in halves (144 B)

// scratch (allocation-free rule: __device__ globals)
__device__ float    g_dinv[NMAX];
__device__ float    g_h[NMAX * H];      // h fp32 (residual; node-local)
__device__ __half   g_hh[NMAX * H];     // h fp16 (conv_mma input)
__device__ __half   g_th[NMAX * H];     // t fp16 (messages)
__device__ __half   g_wh[3 * H * H];    // W_conv transposed fp16: [l][n][k]
__device__ int      g_cnt[NMAX];
__device__ int      g_rowptr[NMAX + 1];
__device__ int      g_wr[NMAX];
__device__ __align__(16) unsigned g_se[EPADMAX];  // {norm:f16 <<16 | src:u16}; rows padded to 8
__device__ int      g_bsum[64];

// ---------------- W pre-convert ----------------

__global__ void convW(const float* __restrict__ W) {
    int i = blockIdx.x * blockDim.x + threadIdx.x;
    if (i >= 3 * H * H) return;
    int l = i >> 12, rem = i & 4095, n = rem >> 6, k = rem & 63;
    g_wh[i] = __float2half_rn(W[l * H * H + k * H + n]);
}

// ---------------- CSR build ----------------

__global__ void count_kernel(const int* __restrict__ col, int E) {
    int e = blockIdx.x * blockDim.x + threadIdx.x;
    if (e < E) atomicAdd(&g_cnt[col[e]], 1);
}

__global__ void scanA(int N) {
    __shared__ int wsum[32];
    __shared__ int wpre[32];
    int tid = threadIdx.x, lane = tid & 31, w = tid >> 5;
    int i = blockIdx.x * 1024 + tid;
    int v = (i < N) ? ((g_cnt[i] + 7) & ~7) : 0;
    int x = v;
#pragma unroll
    for (int o = 1; o < 32; o <<= 1) {
        int t = __shfl_up_sync(0xFFFFFFFFu, x, o);
        if (lane >= o) x += t;
    }
    if (lane == 31) wsum[w] = x;
    __syncthreads();
    if (w == 0) {
        int y = wsum[lane];
#pragma unroll
        for (int o = 1; o < 32; o <<= 1) {
            int t = __shfl_up_sync(0xFFFFFFFFu, y, o);
            if (lane >= o) y += t;
        }
        wpre[lane] = y - wsum[lane];
        if (lane == 31) g_bsum[blockIdx.x] = y;
    }
    __syncthreads();
    if (i < N) g_rowptr[i] = wpre[w] + x - v;
}

__global__ void scanC(int N) {
    __shared__ int sbase;
    int i = blockIdx.x * 256 + threadIdx.x;
    int seg = (blockIdx.x * 256) >> 10;
    if (threadIdx.x < 32) {
        int l = threadIdx.x;
        int v = ((l < seg) ? g_bsum[l] : 0) + ((l + 32 < seg) ? g_bsum[l + 32] : 0);
#pragma unroll
        for (int o = 16; o; o >>= 1) v += __shfl_xor_sync(0xFFFFFFFFu, v, o);
        if (l == 0) sbase = v;
    }
    __syncthreads();
    if (i < N) {
        int rp = g_rowptr[i] + sbase;
        g_rowptr[i] = rp;
        g_wr[i] = rp;
        g_dinv[i] = rsqrtf((float)g_cnt[i] + 1.0f);
        if (i == N - 1) g_rowptr[N] = rp + ((g_cnt[i] + 7) & ~7);
    }
}

__global__ void build_kernel(const int* __restrict__ ei, int E) {
    int e = blockIdx.x * blockDim.x + threadIdx.x;
    if (e >= E) return;
    int r = ei[e], c = ei[E + e];
    int slot = atomicAdd(&g_wr[c], 1);
    __half nh = __float2half_rn(g_dinv[r] * g_dinv[c]);
    g_se[slot] = ((unsigned)__half_as_ushort(nh) << 16) | (unsigned)r;
}

// ---------------- input GEMM: h = relu(x @ W_in + b_in); writes fp32 + fp16 ----------------

__global__ void __launch_bounds__(256) in_gemm(const float* __restrict__ x,
                                               const float* __restrict__ Win,
                                               const float* __restrict__ bin, int N) {
    __shared__ __align__(16) float sx[64][IN_DIM];
    int tid = threadIdx.x;
    int j = tid & 63, sub = tid >> 6;
    int base = blockIdx.x * 64;
    int nn = N - base;
    if (nn > 64) nn = 64;
    if (nn <= 0) return;

    float w[IN_DIM];
#pragma unroll
    for (int k = 0; k < IN_DIM; k++) w[k] = Win[k * H + j];
    float bj = bin[j];

    const float4* xsrc = (const float4*)&x[base * IN_DIM];
    float4* sdst = (float4*)sx;
    int nvec = nn * (IN_DIM / 4);
    for (int i = tid; i < nvec; i += 256) sdst[i] = xsrc[i];
    __syncthreads();

    for (int n = sub; n < nn; n += 4) {
        const float4* sp = (const float4*)&sx[n][0];
        float4 s0 = sp[0], s1 = sp[1], s2 = sp[2], s3 = sp[3];
        float acc = bj;
        acc += s0.x * w[0]  + s0.y * w[1]  + s0.z * w[2]  + s0.w * w[3];
        acc += s1.x * w[4]  + s1.y * w[5]  + s1.z * w[6]  + s1.w * w[7];
        acc += s2.x * w[8]  + s2.y * w[9]  + s2.z * w[10] + s2.w * w[11];
        acc += s3.x * w[12] + s3.y * w[13] + s3.z * w[14] + s3.w * w[15];
        acc = fmaxf(acc, 0.0f);
        g_h[(base + n) * H + j] = acc;
        g_hh[(base + n) * H + j] = __float2half_rn(acc);
    }
}

// ---------------- per-layer transform: t = hh @ W via mma.sync (all-fp16 tiles) ----------------

__global__ void __launch_bounds__(256) conv_mma(int layer, int N) {
    __shared__ __half sH[128 * SHS];
    __shared__ __half sWT[64 * SHS];
    int tid = threadIdx.x;
    int base = blockIdx.x * 128;

    // W tile copy (fp16, pre-transposed): 64 rows x 8 uint4
    {
        const uint4* wsrc = (const uint4*)&g_wh[layer * H * H];
        for (int i = tid; i < 512; i += 256) {
            int row = i >> 3, q = i & 7;
            *(uint4*)&sWT[row * SHS + q * 8] = wsrc[row * 8 + q];
        }
    }
    // h tile copy (fp16 direct): 128 rows x 8 uint4 (zero-pad OOB)
    {
        const uint4* hsrc = (const uint4*)&g_hh[base * H];
        int nn = N - base; if (nn > 128) nn = 128;
        int nvec = nn * 8;
        for (int i = tid; i < 1024; i += 256) {
            int row = i >> 3, q = i & 7;
            uint4 v = (i < nvec) ? hsrc[i] : make_uint4(0u, 0u, 0u, 0u);
            *(uint4*)&sH[row * SHS + q * 8] = v;
        }
    }
    __syncthreads();

    int w = tid >> 5, lane = tid & 31;
    int m0 = w * 16;

    float acc[8][4];
#pragma unroll
    for (int nt = 0; nt < 8; nt++)
#pragma unroll
        for (int q = 0; q < 4; q++) acc[nt][q] = 0.0f;

    unsigned a_base = (unsigned)__cvta_generic_to_shared(
        &sH[(m0 + (lane & 15)) * SHS + ((lane >> 4) & 1) * 8]);
    int bm = lane >> 3, brow = lane & 7;

#pragma unroll
    for (int kk = 0; kk < 64; kk += 16) {
        unsigned a0, a1, a2, a3;
        asm volatile("ldmatrix.sync.aligned.m8n8.x4.shared.b16 {%0,%1,%2,%3}, [%4];"
                     : "=r"(a0), "=r"(a1), "=r"(a2), "=r"(a3)
                     : "r"(a_base + kk * 2));
#pragma unroll
        for (int g = 0; g < 4; g++) {
            unsigned b_addr = (unsigned)__cvta_generic_to_shared(
                &sWT[((2 * g + (bm >> 1)) * 8 + brow) * SHS + kk + (bm & 1) * 8]);
            unsigned b0, b1, b2, b3;
            asm volatile("ldmatrix.sync.aligned.m8n8.x4.shared.b16 {%0,%1,%2,%3}, [%4];"
                         : "=r"(b0), "=r"(b1), "=r"(b2), "=r"(b3) : "r"(b_addr));
            int t0 = 2 * g, t1 = 2 * g + 1;
            asm volatile("mma.sync.aligned.m16n8k16.row.col.f32.f16.f16.f32 "
                         "{%0,%1,%2,%3}, {%4,%5,%6,%7}, {%8,%9}, {%0,%1,%2,%3};"
                         : "+f"(acc[t0][0]), "+f"(acc[t0][1]), "+f"(acc[t0][2]), "+f"(acc[t0][3])
                         : "r"(a0), "r"(a1), "r"(a2), "r"(a3), "r"(b0), "r"(b1));
            asm volatile("mma.sync.aligned.m16n8k16.row.col.f32.f16.f16.f32 "
                         "{%0,%1,%2,%3}, {%4,%5,%6,%7}, {%8,%9}, {%0,%1,%2,%3};"
                         : "+f"(acc[t1][0]), "+f"(acc[t1][1]), "+f"(acc[t1][2]), "+f"(acc[t1][3])
                         : "r"(a0), "r"(a1), "r"(a2), "r"(a3), "r"(b2), "r"(b3));
        }
    }

    int r0 = base + m0 + (lane >> 2);
    int r1 = r0 + 8;
#pragma unroll
    for (int nt = 0; nt < 8; nt++) {
        int c = nt * 8 + (lane & 3) * 2;
        __half2 p01 = __floats2half2_rn(acc[nt][0], acc[nt][1]);
        __half2 p23 = __floats2half2_rn(acc[nt][2], acc[nt][3]);
        if (r0 < N) *(__half2*)&g_th[r0 * H + c] = p01;
        if (r1 < N) *(__half2*)&g_th[r1 * H + c] = p23;
    }
}

// ---------------- fused gather + bias + self-loop + LN + ReLU + residual (+ head) ----------------
// one warp per node; lane owns features (2*lane, 2*lane+1); messages read as half2.

__device__ __forceinline__ void unpack_se(unsigned m, int& src, float& nm) {
    src = (int)(m & 0xFFFFu);
    nm = __half2float(__ushort_as_half((unsigned short)(m >> 16)));
}

__global__ void gather_ln(const float* __restrict__ b,
                          const float* __restrict__ gamma, const float* __restrict__ beta,
                          const float* __restrict__ Wout, const float* __restrict__ bout,
                          float* __restrict__ out, int N, int last) {
    int node = (blockIdx.x * blockDim.x + threadIdx.x) >> 5;
    int lane = threadIdx.x & 31;
    if (node >= N) return;

    const __half2* t2 = (const __half2*)g_th;
    float d = g_dinv[node];
    float2 b2 = ((const float2*)b)[lane];
    float2 tn = __half22float2(t2[node * 32 + lane]);
    float accx = b2.x + tn.x * d * d;
    float accy = b2.y + tn.y * d * d;

    int s = g_rowptr[node], e = g_rowptr[node + 1];
    for (int j = s; j < e; j += 8) {
        const uint4* mp = (const uint4*)&g_se[j];
        uint4 ma = mp[0], mb = mp[1];
        int r0, r1, r2, r3, r4, r5, r6, r7;
        float n0, n1, n2, n3, n4, n5, n6, n7;
        unpack_se(ma.x, r0, n0); unpack_se(ma.y, r1, n1);
        unpack_se(ma.z, r2, n2); unpack_se(ma.w, r3, n3);
        unpack_se(mb.x, r4, n4); unpack_se(mb.y, r5, n5);
        unpack_se(mb.z, r6, n6); unpack_se(mb.w, r7, n7);
        float2 v0 = __half22float2(t2[r0 * 32 + lane]);
        float2 v1 = __half22float2(t2[r1 * 32 + lane]);
        float2 v2 = __half22float2(t2[r2 * 32 + lane]);
        float2 v3 = __half22float2(t2[r3 * 32 + lane]);
        float2 v4 = __half22float2(t2[r4 * 32 + lane]);
        float2 v5 = __half22float2(t2[r5 * 32 + lane]);
        float2 v6 = __half22float2(t2[r6 * 32 + lane]);
        float2 v7 = __half22float2(t2[r7 * 32 + lane]);
        accx += v0.x * n0 + v1.x * n1 + v2.x * n2 + v3.x * n3
              + v4.x * n4 + v5.x * n5 + v6.x * n6 + v7.x * n7;
        accy += v0.y * n0 + v1.y * n1 + v2.y * n2 + v3.y * n3
              + v4.y * n4 + v5.y * n5 + v6.y * n6 + v7.y * n7;
    }

    // layernorm over 64 features
    float ssum = accx + accy;
#pragma unroll
    for (int o = 16; o; o >>= 1) ssum += __shfl_xor_sync(0xFFFFFFFFu, ssum, o);
    float mu = ssum * (1.0f / 64.0f);
    float dx = accx - mu, dy = accy - mu;
    float var = dx * dx + dy * dy;
#pragma unroll
    for (int o = 16; o; o >>= 1) var += __shfl_xor_sync(0xFFFFFFFFu, var, o);
    float inv = rsqrtf(var * (1.0f / 64.0f) + 1e-5f);

    float2 g2 = ((const float2*)gamma)[lane];
    float2 be2 = ((const float2*)beta)[lane];
    float2* hp = (float2*)&g_h[node * H];
    float2 hres = hp[lane];
    float r0 = fmaxf(dx * inv * g2.x + be2.x, 0.0f) + hres.x;
    float r1 = fmaxf(dy * inv * g2.y + be2.y, 0.0f) + hres.y;
    hp[lane] = make_float2(r0, r1);
    ((__half2*)&g_hh[node * H])[lane] = __floats2half2_rn(r0, r1);

    if (last) {
        float2 w2 = ((const float2*)Wout)[lane];
        float o_ = r0 * w2.x + r1 * w2.y;
#pragma unroll
        for (int o = 16; o; o >>= 1) o_ += __shfl_xor_sync(0xFFFFFFFFu, o_, o);
        if (lane == 0) out[node] = o_ + bout[0];
    }
}

// ---------------- launch ----------------

extern "C" void kernel_launch(void* const* d_in, const int* in_sizes, int n_in,
                              void* d_out, int out_size) {
    const float* x      = (const float*)d_in[0];
    const int*   ei     = (const int*)d_in[1];
    const float* W_in   = (const float*)d_in[2];
    const float* b_in   = (const float*)d_in[3];
    const float* W_conv = (const float*)d_in[4];
    const float* b_conv = (const float*)d_in[5];
    const float* gamma  = (const float*)d_in[6];
    const float* beta   = (const float*)d_in[7];
    const float* W_out  = (const float*)d_in[8];
    const float* b_out  = (const float*)d_in[9];
    float* out = (float*)d_out;

    int N = in_sizes[0] / IN_DIM;
    int E = in_sizes[1] / 2;
    int nblk_scan = (N + 1023) / 1024;

    cudaStream_t s2;
    cudaStreamCreate(&s2);
    cudaEvent_t e0, e1;
    cudaEventCreate(&e0);
    cudaEventCreate(&e1);

    // branch A part 1: CSR counts
    void* cnt_ptr = nullptr; void* se_ptr = nullptr;
    cudaGetSymbolAddress(&cnt_ptr, g_cnt);
    cudaGetSymbolAddress(&se_ptr, g_se);
    cudaMemsetAsync(cnt_ptr, 0, (size_t)N * sizeof(int));
    size_t se_bytes = (size_t)E * sizeof(unsigned) + (size_t)N * 8 * sizeof(unsigned);
    if (se_bytes > (size_t)EPADMAX * sizeof(unsigned)) se_bytes = (size_t)EPADMAX * sizeof(unsigned);
    cudaMemsetAsync(se_ptr, 0, se_bytes);
    count_kernel<<<(E + 255) / 256, 256>>>(ei + E, E);
    scanA<<<nblk_scan, 1024>>>(N);

    // fork branch B (independent): W convert + input GEMM + layer-0 transform
    cudaEventRecord(e0, 0);
    cudaStreamWaitEvent(s2, e0, 0);
    convW<<<48, 256, 0, s2>>>(W_conv);
    in_gemm<<<(N + 63) / 64, 256, 0, s2>>>(x, W_in, b_in, N);
    conv_mma<<<(N + 127) / 128, 256, 0, s2>>>(0, N);
    cudaEventRecord(e1, s2);

    // branch A part 2
    scanC<<<(N + 255) / 256, 256>>>(N);
    build_kernel<<<(E + 255) / 256, 256>>>(ei, E);

    // join
    cudaStreamWaitEvent(0, e1, 0);

    for (int l = 0; l < 3; l++) {
        if (l > 0) conv_mma<<<(N + 127) / 128, 256>>>(l, N);
        gather_ln<<<(N + 7) / 8, 256>>>(b_conv + l * H, gamma + l * H, beta + l * H,
                                        W_out, b_out, out, N, l == 2);
    }

    cudaEventDestroy(e0);
    cudaEventDestroy(e1);
    cudaStreamDestroy(s2);
}

// round 16
// speedup vs baseline: 1.3091x; 1.0768x over previous
#include <cuda_runtime.h>
#include <cuda_fp16.h>

#define H 64
#define IN_DIM 16
#define NMAX 50048
#define EPADMAX 1200000
#define SHS 72  // padded smem row stride in halves (144 B)

// scratch (allocation-free rule: __device__ globals)
__device__ float    g_dinv[NMAX];
__device__ float    g_h[NMAX * H];      // h fp32 (residual; node-local)
__device__ __half   g_hh[NMAX * H];     // h fp16 (conv_mma input)
__device__ __half   g_th[NMAX * H];     // t_scaled fp16 (= dinv[r] * (h@W)[r]); row N stays zero forever
__device__ __half   g_wh[3 * H * H];    // W_conv transposed fp16: [l][n][k]
__device__ int      g_cnt[NMAX];
__device__ int      g_rowptr[NMAX + 1];
__device__ int      g_wr[NMAX];
__device__ __align__(16) unsigned short g_se[EPADMAX];  // u16 src; rows padded to 8 (pads -> N)
__device__ int      g_bsum[64];

// ---------------- W pre-convert ----------------

__global__ void convW(const float* __restrict__ W) {
    int i = blockIdx.x * blockDim.x + threadIdx.x;
    if (i >= 3 * H * H) return;
    int l = i >> 12, rem = i & 4095, n = rem >> 6, k = rem & 63;
    g_wh[i] = __float2half_rn(W[l * H * H + k * H + n]);
}

// ---------------- CSR build ----------------

__global__ void count_kernel(const int* __restrict__ col, int E) {
    int e = blockIdx.x * blockDim.x + threadIdx.x;
    if (e < E) atomicAdd(&g_cnt[col[e]], 1);
}

__global__ void scanA(int N) {
    __shared__ int wsum[32];
    __shared__ int wpre[32];
    int tid = threadIdx.x, lane = tid & 31, w = tid >> 5;
    int i = blockIdx.x * 1024 + tid;
    int v = (i < N) ? ((g_cnt[i] + 7) & ~7) : 0;
    int x = v;
#pragma unroll
    for (int o = 1; o < 32; o <<= 1) {
        int t = __shfl_up_sync(0xFFFFFFFFu, x, o);
        if (lane >= o) x += t;
    }
    if (lane == 31) wsum[w] = x;
    __syncthreads();
    if (w == 0) {
        int y = wsum[lane];
#pragma unroll
        for (int o = 1; o < 32; o <<= 1) {
            int t = __shfl_up_sync(0xFFFFFFFFu, y, o);
            if (lane >= o) y += t;
        }
        wpre[lane] = y - wsum[lane];
        if (lane == 31) g_bsum[blockIdx.x] = y;
    }
    __syncthreads();
    if (i < N) g_rowptr[i] = wpre[w] + x - v;
}

// finalize rowptr + dinv + fill pad slots with zero-row index N
__global__ void scanC(int N) {
    __shared__ int sbase;
    int i = blockIdx.x * 256 + threadIdx.x;
    int seg = (blockIdx.x * 256) >> 10;
    if (threadIdx.x < 32) {
        int l = threadIdx.x;
        int v = ((l < seg) ? g_bsum[l] : 0) + ((l + 32 < seg) ? g_bsum[l + 32] : 0);
#pragma unroll
        for (int o = 16; o; o >>= 1) v += __shfl_xor_sync(0xFFFFFFFFu, v, o);
        if (l == 0) sbase = v;
    }
    __syncthreads();
    if (i < N) {
        int cnt = g_cnt[i];
        int rp = g_rowptr[i] + sbase;
        g_rowptr[i] = rp;
        g_wr[i] = rp;
        g_dinv[i] = rsqrtf((float)cnt + 1.0f);
        int pend = rp + ((cnt + 7) & ~7);
        for (int k = rp + cnt; k < pend; k++) g_se[k] = (unsigned short)N;  // zero row
        if (i == N - 1) g_rowptr[N] = pend;
    }
}

__global__ void build_kernel(const int* __restrict__ ei, int E) {
    int e = blockIdx.x * blockDim.x + threadIdx.x;
    if (e >= E) return;
    int r = ei[e], c = ei[E + e];
    int slot = atomicAdd(&g_wr[c], 1);
    g_se[slot] = (unsigned short)r;  // src < 65536
}

// ---------------- input GEMM: h = relu(x @ W_in + b_in); writes fp32 + fp16 ----------------

__global__ void __launch_bounds__(256) in_gemm(const float* __restrict__ x,
                                               const float* __restrict__ Win,
                                               const float* __restrict__ bin, int N) {
    __shared__ __align__(16) float sx[64][IN_DIM];
    int tid = threadIdx.x;
    int j = tid & 63, sub = tid >> 6;
    int base = blockIdx.x * 64;
    int nn = N - base;
    if (nn > 64) nn = 64;
    if (nn <= 0) return;

    float w[IN_DIM];
#pragma unroll
    for (int k = 0; k < IN_DIM; k++) w[k] = Win[k * H + j];
    float bj = bin[j];

    const float4* xsrc = (const float4*)&x[base * IN_DIM];
    float4* sdst = (float4*)sx;
    int nvec = nn * (IN_DIM / 4);
    for (int i = tid; i < nvec; i += 256) sdst[i] = xsrc[i];
    __syncthreads();

    for (int n = sub; n < nn; n += 4) {
        const float4* sp = (const float4*)&sx[n][0];
        float4 s0 = sp[0], s1 = sp[1], s2 = sp[2], s3 = sp[3];
        float acc = bj;
        acc += s0.x * w[0]  + s0.y * w[1]  + s0.z * w[2]  + s0.w * w[3];
        acc += s1.x * w[4]  + s1.y * w[5]  + s1.z * w[6]  + s1.w * w[7];
        acc += s2.x * w[8]  + s2.y * w[9]  + s2.z * w[10] + s2.w * w[11];
        acc += s3.x * w[12] + s3.y * w[13] + s3.z * w[14] + s3.w * w[15];
        acc = fmaxf(acc, 0.0f);
        g_h[(base + n) * H + j] = acc;
        g_hh[(base + n) * H + j] = __float2half_rn(acc);
    }
}

// ---------------- per-layer transform: t_s = dinv .* (hh @ W) via mma.sync ----------------

__global__ void __launch_bounds__(256) conv_mma(int layer, int N) {
    __shared__ __half sH[128 * SHS];
    __shared__ __half sWT[64 * SHS];
    int tid = threadIdx.x;
    int base = blockIdx.x * 128;

    // W tile copy (fp16, pre-transposed): 64 rows x 8 uint4
    {
        const uint4* wsrc = (const uint4*)&g_wh[layer * H * H];
        for (int i = tid; i < 512; i += 256) {
            int row = i >> 3, q = i & 7;
            *(uint4*)&sWT[row * SHS + q * 8] = wsrc[row * 8 + q];
        }
    }
    // h tile copy (fp16 direct): 128 rows x 8 uint4 (zero-pad OOB)
    {
        const uint4* hsrc = (const uint4*)&g_hh[base * H];
        int nn = N - base; if (nn > 128) nn = 128;
        int nvec = nn * 8;
        for (int i = tid; i < 1024; i += 256) {
            int row = i >> 3, q = i & 7;
            uint4 v = (i < nvec) ? hsrc[i] : make_uint4(0u, 0u, 0u, 0u);
            *(uint4*)&sH[row * SHS + q * 8] = v;
        }
    }
    __syncthreads();

    int w = tid >> 5, lane = tid & 31;
    int m0 = w * 16;

    float acc[8][4];
#pragma unroll
    for (int nt = 0; nt < 8; nt++)
#pragma unroll
        for (int q = 0; q < 4; q++) acc[nt][q] = 0.0f;

    unsigned a_base = (unsigned)__cvta_generic_to_shared(
        &sH[(m0 + (lane & 15)) * SHS + ((lane >> 4) & 1) * 8]);
    int bm = lane >> 3, brow = lane & 7;

#pragma unroll
    for (int kk = 0; kk < 64; kk += 16) {
        unsigned a0, a1, a2, a3;
        asm volatile("ldmatrix.sync.aligned.m8n8.x4.shared.b16 {%0,%1,%2,%3}, [%4];"
                     : "=r"(a0), "=r"(a1), "=r"(a2), "=r"(a3)
                     : "r"(a_base + kk * 2));
#pragma unroll
        for (int g = 0; g < 4; g++) {
            unsigned b_addr = (unsigned)__cvta_generic_to_shared(
                &sWT[((2 * g + (bm >> 1)) * 8 + brow) * SHS + kk + (bm & 1) * 8]);
            unsigned b0, b1, b2, b3;
            asm volatile("ldmatrix.sync.aligned.m8n8.x4.shared.b16 {%0,%1,%2,%3}, [%4];"
                         : "=r"(b0), "=r"(b1), "=r"(b2), "=r"(b3) : "r"(b_addr));
            int t0 = 2 * g, t1 = 2 * g + 1;
            asm volatile("mma.sync.aligned.m16n8k16.row.col.f32.f16.f16.f32 "
                         "{%0,%1,%2,%3}, {%4,%5,%6,%7}, {%8,%9}, {%0,%1,%2,%3};"
                         : "+f"(acc[t0][0]), "+f"(acc[t0][1]), "+f"(acc[t0][2]), "+f"(acc[t0][3])
                         : "r"(a0), "r"(a1), "r"(a2), "r"(a3), "r"(b0), "r"(b1));
            asm volatile("mma.sync.aligned.m16n8k16.row.col.f32.f16.f16.f32 "
                         "{%0,%1,%2,%3}, {%4,%5,%6,%7}, {%8,%9}, {%0,%1,%2,%3};"
                         : "+f"(acc[t1][0]), "+f"(acc[t1][1]), "+f"(acc[t1][2]), "+f"(acc[t1][3])
                         : "r"(a0), "r"(a1), "r"(a2), "r"(a3), "r"(b2), "r"(b3));
        }
    }

    // epilogue: scale rows by dinv[row], store fp16
    int r0 = base + m0 + (lane >> 2);
    int r1 = r0 + 8;
    float dv0 = (r0 < N) ? g_dinv[r0] : 0.0f;
    float dv1 = (r1 < N) ? g_dinv[r1] : 0.0f;
#pragma unroll
    for (int nt = 0; nt < 8; nt++) {
        int c = nt * 8 + (lane & 3) * 2;
        __half2 p01 = __floats2half2_rn(acc[nt][0] * dv0, acc[nt][1] * dv0);
        __half2 p23 = __floats2half2_rn(acc[nt][2] * dv1, acc[nt][3] * dv1);
        if (r0 < N) *(__half2*)&g_th[r0 * H + c] = p01;
        if (r1 < N) *(__half2*)&g_th[r1 * H + c] = p23;
    }
}

// ---------------- fused gather + self-loop + bias + LN + ReLU + residual (+ head) --------
// one warp per node; lane owns features (2*lane, 2*lane+1).
// agg = dinv[c] * (t_s[c] + sum_src t_s[src]) + b   (t_s pre-scaled by dinv[src])

__global__ void gather_ln(const float* __restrict__ b,
                          const float* __restrict__ gamma, const float* __restrict__ beta,
                          const float* __restrict__ Wout, const float* __restrict__ bout,
                          float* __restrict__ out, int N, int last) {
    int node = (blockIdx.x * blockDim.x + threadIdx.x) >> 5;
    int lane = threadIdx.x & 31;
    if (node >= N) return;

    const __half2* t2 = (const __half2*)g_th;
    float2 tn = __half22float2(t2[node * 32 + lane]);
    float accx = tn.x, accy = tn.y;  // self-loop (pre-scaled)

    int s = g_rowptr[node], e = g_rowptr[node + 1];
    for (int j = s; j < e; j += 8) {
        const uint4* mp = (const uint4*)&g_se[j];  // 8 x u16
        uint4 m = mp[0];
        int r0 = m.x & 0xFFFF, r1 = m.x >> 16;
        int r2 = m.y & 0xFFFF, r3 = m.y >> 16;
        int r4 = m.z & 0xFFFF, r5 = m.z >> 16;
        int r6 = m.w & 0xFFFF, r7 = m.w >> 16;
        float2 v0 = __half22float2(t2[r0 * 32 + lane]);
        float2 v1 = __half22float2(t2[r1 * 32 + lane]);
        float2 v2 = __half22float2(t2[r2 * 32 + lane]);
        float2 v3 = __half22float2(t2[r3 * 32 + lane]);
        float2 v4 = __half22float2(t2[r4 * 32 + lane]);
        float2 v5 = __half22float2(t2[r5 * 32 + lane]);
        float2 v6 = __half22float2(t2[r6 * 32 + lane]);
        float2 v7 = __half22float2(t2[r7 * 32 + lane]);
        accx += v0.x + v1.x + v2.x + v3.x + v4.x + v5.x + v6.x + v7.x;
        accy += v0.y + v1.y + v2.y + v3.y + v4.y + v5.y + v6.y + v7.y;
    }

    float d = g_dinv[node];
    float2 b2 = ((const float2*)b)[lane];
    accx = b2.x + d * accx;
    accy = b2.y + d * accy;

    // layernorm over 64 features
    float ssum = accx + accy;
#pragma unroll
    for (int o = 16; o; o >>= 1) ssum += __shfl_xor_sync(0xFFFFFFFFu, ssum, o);
    float mu = ssum * (1.0f / 64.0f);
    float dx = accx - mu, dy = accy - mu;
    float var = dx * dx + dy * dy;
#pragma unroll
    for (int o = 16; o; o >>= 1) var += __shfl_xor_sync(0xFFFFFFFFu, var, o);
    float inv = rsqrtf(var * (1.0f / 64.0f) + 1e-5f);

    float2 g2 = ((const float2*)gamma)[lane];
    float2 be2 = ((const float2*)beta)[lane];
    float2* hp = (float2*)&g_h[node * H];
    float2 hres = hp[lane];
    float r0 = fmaxf(dx * inv * g2.x + be2.x, 0.0f) + hres.x;
    float r1 = fmaxf(dy * inv * g2.y + be2.y, 0.0f) + hres.y;
    hp[lane] = make_float2(r0, r1);
    ((__half2*)&g_hh[node * H])[lane] = __floats2half2_rn(r0, r1);

    if (last) {
        float2 w2 = ((const float2*)Wout)[lane];
        float o_ = r0 * w2.x + r1 * w2.y;
#pragma unroll
        for (int o = 16; o; o >>= 1) o_ += __shfl_xor_sync(0xFFFFFFFFu, o_, o);
        if (lane == 0) out[node] = o_ + bout[0];
    }
}

// ---------------- launch ----------------

extern "C" void kernel_launch(void* const* d_in, const int* in_sizes, int n_in,
                              void* d_out, int out_size) {
    const float* x      = (const float*)d_in[0];
    const int*   ei     = (const int*)d_in[1];
    const float* W_in   = (const float*)d_in[2];
    const float* b_in   = (const float*)d_in[3];
    const float* W_conv = (const float*)d_in[4];
    const float* b_conv = (const float*)d_in[5];
    const float* gamma  = (const float*)d_in[6];
    const float* beta   = (const float*)d_in[7];
    const float* W_out  = (const float*)d_in[8];
    const float* b_out  = (const float*)d_in[9];
    float* out = (float*)d_out;

    int N = in_sizes[0] / IN_DIM;
    int E = in_sizes[1] / 2;
    int nblk_scan = (N + 1023) / 1024;

    cudaStream_t s2;
    cudaStreamCreate(&s2);
    cudaEvent_t e0, e1;
    cudaEventCreate(&e0);
    cudaEventCreate(&e1);

    // branch A part 1: CSR counts
    void* cnt_ptr = nullptr;
    cudaGetSymbolAddress(&cnt_ptr, g_cnt);
    cudaMemsetAsync(cnt_ptr, 0, (size_t)N * sizeof(int));
    count_kernel<<<(E + 255) / 256, 256>>>(ei + E, E);
    scanA<<<nblk_scan, 1024>>>(N);

    // fork branch B (independent): W convert + input GEMM + layer-0 transform
    cudaEventRecord(e0, 0);
    cudaStreamWaitEvent(s2, e0, 0);
    convW<<<48, 256, 0, s2>>>(W_conv);
    in_gemm<<<(N + 63) / 64, 256, 0, s2>>>(x, W_in, b_in, N);
    cudaEventRecord(e1, s2);

    // branch A part 2 (scanC needs only counts; build needs rowptr)
    scanC<<<(N + 255) / 256, 256>>>(N);
    build_kernel<<<(E + 255) / 256, 256>>>(ei, E);

    // join (conv0 needs dinv from scanC, so it runs after join on stream 0)
    cudaStreamWaitEvent(0, e1, 0);

    for (int l = 0; l < 3; l++) {
        conv_mma<<<(N + 127) / 128, 256>>>(l, N);
        gather_ln<<<(N + 7) / 8, 256>>>(b_conv + l * H, gamma + l * H, beta + l * H,
                                        W_out, b_out, out, N, l == 2);
    }

    cudaEventDestroy(e0);
    cudaEventDestroy(e1);
    cudaStreamDestroy(s2);
}

// round 17
// speedup vs baseline: 1.3839x; 1.0571x over previous
#include <cuda_runtime.h>
#include <cuda_fp16.h>

#define H 64
#define IN_DIM 16
#define NMAX 50048
#define EPADMAX 1200000
#define SHS 72  // padded smem row stride in halves (144 B)

// scratch (allocation-free rule: __device__ globals)
__device__ float    g_dinv[NMAX];
__device__ float    g_h[NMAX * H];      // h fp32 (residual; node-local)
__device__ __half   g_hh[NMAX * H];     // h fp16 (conv_mma input)
__device__ __half   g_th[NMAX * H];     // t_scaled fp16 (= dinv[r] * (h@W)[r]); row N stays zero forever
__device__ __half   g_wh[3 * H * H];    // W_conv transposed fp16: [l][n][k]
__device__ int      g_cnt[NMAX];
__device__ int      g_rowptr[NMAX + 1];
__device__ int      g_wr[NMAX];
__device__ __align__(16) unsigned short g_se[EPADMAX];  // u16 src; rows padded to 8 (pads -> N)
__device__ int      g_bsum[64];

// ---------------- W pre-convert ----------------

__global__ void convW(const float* __restrict__ W) {
    int i = blockIdx.x * blockDim.x + threadIdx.x;
    if (i >= 3 * H * H) return;
    int l = i >> 12, rem = i & 4095, n = rem >> 6, k = rem & 63;
    g_wh[i] = __float2half_rn(W[l * H * H + k * H + n]);
}

// ---------------- CSR build ----------------

__global__ void count_kernel(const int* __restrict__ col, int E) {
    int e = blockIdx.x * blockDim.x + threadIdx.x;
    if (e < E) atomicAdd(&g_cnt[col[e]], 1);
}

__global__ void scanA(int N) {
    __shared__ int wsum[32];
    __shared__ int wpre[32];
    int tid = threadIdx.x, lane = tid & 31, w = tid >> 5;
    int i = blockIdx.x * 1024 + tid;
    int v = (i < N) ? ((g_cnt[i] + 7) & ~7) : 0;
    int x = v;
#pragma unroll
    for (int o = 1; o < 32; o <<= 1) {
        int t = __shfl_up_sync(0xFFFFFFFFu, x, o);
        if (lane >= o) x += t;
    }
    if (lane == 31) wsum[w] = x;
    __syncthreads();
    if (w == 0) {
        int y = wsum[lane];
#pragma unroll
        for (int o = 1; o < 32; o <<= 1) {
            int t = __shfl_up_sync(0xFFFFFFFFu, y, o);
            if (lane >= o) y += t;
        }
        wpre[lane] = y - wsum[lane];
        if (lane == 31) g_bsum[blockIdx.x] = y;
    }
    __syncthreads();
    if (i < N) g_rowptr[i] = wpre[w] + x - v;
}

// finalize rowptr + dinv + fill pad slots with zero-row index N
__global__ void scanC(int N) {
    __shared__ int sbase;
    int i = blockIdx.x * 256 + threadIdx.x;
    int seg = (blockIdx.x * 256) >> 10;
    if (threadIdx.x < 32) {
        int l = threadIdx.x;
        int v = ((l < seg) ? g_bsum[l] : 0) + ((l + 32 < seg) ? g_bsum[l + 32] : 0);
#pragma unroll
        for (int o = 16; o; o >>= 1) v += __shfl_xor_sync(0xFFFFFFFFu, v, o);
        if (l == 0) sbase = v;
    }
    __syncthreads();
    if (i < N) {
        int cnt = g_cnt[i];
        int rp = g_rowptr[i] + sbase;
        g_rowptr[i] = rp;
        g_wr[i] = rp;
        g_dinv[i] = rsqrtf((float)cnt + 1.0f);
        int pend = rp + ((cnt + 7) & ~7);
        for (int k = rp + cnt; k < pend; k++) g_se[k] = (unsigned short)N;  // zero row
        if (i == N - 1) g_rowptr[N] = pend;
    }
}

__global__ void build_kernel(const int* __restrict__ ei, int E) {
    int e = blockIdx.x * blockDim.x + threadIdx.x;
    if (e >= E) return;
    int r = ei[e], c = ei[E + e];
    int slot = atomicAdd(&g_wr[c], 1);
    g_se[slot] = (unsigned short)r;  // src < 65536
}

// ---------------- input GEMM: h = relu(x @ W_in + b_in); writes fp32 + fp16 ----------------

__global__ void __launch_bounds__(256) in_gemm(const float* __restrict__ x,
                                               const float* __restrict__ Win,
                                               const float* __restrict__ bin, int N) {
    __shared__ __align__(16) float sx[64][IN_DIM];
    int tid = threadIdx.x;
    int j = tid & 63, sub = tid >> 6;
    int base = blockIdx.x * 64;
    int nn = N - base;
    if (nn > 64) nn = 64;
    if (nn <= 0) return;

    float w[IN_DIM];
#pragma unroll
    for (int k = 0; k < IN_DIM; k++) w[k] = Win[k * H + j];
    float bj = bin[j];

    const float4* xsrc = (const float4*)&x[base * IN_DIM];
    float4* sdst = (float4*)sx;
    int nvec = nn * (IN_DIM / 4);
    for (int i = tid; i < nvec; i += 256) sdst[i] = xsrc[i];
    __syncthreads();

    for (int n = sub; n < nn; n += 4) {
        const float4* sp = (const float4*)&sx[n][0];
        float4 s0 = sp[0], s1 = sp[1], s2 = sp[2], s3 = sp[3];
        float acc = bj;
        acc += s0.x * w[0]  + s0.y * w[1]  + s0.z * w[2]  + s0.w * w[3];
        acc += s1.x * w[4]  + s1.y * w[5]  + s1.z * w[6]  + s1.w * w[7];
        acc += s2.x * w[8]  + s2.y * w[9]  + s2.z * w[10] + s2.w * w[11];
        acc += s3.x * w[12] + s3.y * w[13] + s3.z * w[14] + s3.w * w[15];
        acc = fmaxf(acc, 0.0f);
        g_h[(base + n) * H + j] = acc;
        g_hh[(base + n) * H + j] = __float2half_rn(acc);
    }
}

// ---------------- per-layer transform: t_s = dinv .* (hh @ W) via mma.sync ----------------

__global__ void __launch_bounds__(256) conv_mma(int layer, int N) {
    __shared__ __half sH[128 * SHS];
    __shared__ __half sWT[64 * SHS];
    int tid = threadIdx.x;
    int base = blockIdx.x * 128;

    {
        const uint4* wsrc = (const uint4*)&g_wh[layer * H * H];
        for (int i = tid; i < 512; i += 256) {
            int row = i >> 3, q = i & 7;
            *(uint4*)&sWT[row * SHS + q * 8] = wsrc[row * 8 + q];
        }
    }
    {
        const uint4* hsrc = (const uint4*)&g_hh[base * H];
        int nn = N - base; if (nn > 128) nn = 128;
        int nvec = nn * 8;
        for (int i = tid; i < 1024; i += 256) {
            int row = i >> 3, q = i & 7;
            uint4 v = (i < nvec) ? hsrc[i] : make_uint4(0u, 0u, 0u, 0u);
            *(uint4*)&sH[row * SHS + q * 8] = v;
        }
    }
    __syncthreads();

    int w = tid >> 5, lane = tid & 31;
    int m0 = w * 16;

    float acc[8][4];
#pragma unroll
    for (int nt = 0; nt < 8; nt++)
#pragma unroll
        for (int q = 0; q < 4; q++) acc[nt][q] = 0.0f;

    unsigned a_base = (unsigned)__cvta_generic_to_shared(
        &sH[(m0 + (lane & 15)) * SHS + ((lane >> 4) & 1) * 8]);
    int bm = lane >> 3, brow = lane & 7;

#pragma unroll
    for (int kk = 0; kk < 64; kk += 16) {
        unsigned a0, a1, a2, a3;
        asm volatile("ldmatrix.sync.aligned.m8n8.x4.shared.b16 {%0,%1,%2,%3}, [%4];"
                     : "=r"(a0), "=r"(a1), "=r"(a2), "=r"(a3)
                     : "r"(a_base + kk * 2));
#pragma unroll
        for (int g = 0; g < 4; g++) {
            unsigned b_addr = (unsigned)__cvta_generic_to_shared(
                &sWT[((2 * g + (bm >> 1)) * 8 + brow) * SHS + kk + (bm & 1) * 8]);
            unsigned b0, b1, b2, b3;
            asm volatile("ldmatrix.sync.aligned.m8n8.x4.shared.b16 {%0,%1,%2,%3}, [%4];"
                         : "=r"(b0), "=r"(b1), "=r"(b2), "=r"(b3) : "r"(b_addr));
            int t0 = 2 * g, t1 = 2 * g + 1;
            asm volatile("mma.sync.aligned.m16n8k16.row.col.f32.f16.f16.f32 "
                         "{%0,%1,%2,%3}, {%4,%5,%6,%7}, {%8,%9}, {%0,%1,%2,%3};"
                         : "+f"(acc[t0][0]), "+f"(acc[t0][1]), "+f"(acc[t0][2]), "+f"(acc[t0][3])
                         : "r"(a0), "r"(a1), "r"(a2), "r"(a3), "r"(b0), "r"(b1));
            asm volatile("mma.sync.aligned.m16n8k16.row.col.f32.f16.f16.f32 "
                         "{%0,%1,%2,%3}, {%4,%5,%6,%7}, {%8,%9}, {%0,%1,%2,%3};"
                         : "+f"(acc[t1][0]), "+f"(acc[t1][1]), "+f"(acc[t1][2]), "+f"(acc[t1][3])
                         : "r"(a0), "r"(a1), "r"(a2), "r"(a3), "r"(b2), "r"(b3));
        }
    }

    // epilogue: scale rows by dinv[row], store fp16
    int r0 = base + m0 + (lane >> 2);
    int r1 = r0 + 8;
    float dv0 = (r0 < N) ? g_dinv[r0] : 0.0f;
    float dv1 = (r1 < N) ? g_dinv[r1] : 0.0f;
#pragma unroll
    for (int nt = 0; nt < 8; nt++) {
        int c = nt * 8 + (lane & 3) * 2;
        __half2 p01 = __floats2half2_rn(acc[nt][0] * dv0, acc[nt][1] * dv0);
        __half2 p23 = __floats2half2_rn(acc[nt][2] * dv1, acc[nt][3] * dv1);
        if (r0 < N) *(__half2*)&g_th[r0 * H + c] = p01;
        if (r1 < N) *(__half2*)&g_th[r1 * H + c] = p23;
    }
}

// ---------------- fused gather + self-loop + bias + LN + ReLU + residual (+ head) --------
// one warp per node; lane owns features (2*lane, 2*lane+1).
// inner loop: 8 gathers -> 4 HADD2 pair-sums -> fp32 accumulate.

__global__ void gather_ln(const float* __restrict__ b,
                          const float* __restrict__ gamma, const float* __restrict__ beta,
                          const float* __restrict__ Wout, const float* __restrict__ bout,
                          float* __restrict__ out, int N, int last) {
    int node = (blockIdx.x * blockDim.x + threadIdx.x) >> 5;
    int lane = threadIdx.x & 31;
    if (node >= N) return;

    const __half2* t2 = (const __half2*)g_th;
    float2 tn = __half22float2(t2[node * 32 + lane]);
    float accx = tn.x, accy = tn.y;  // self-loop (pre-scaled)

    int s = g_rowptr[node], e = g_rowptr[node + 1];
    for (int j = s; j < e; j += 8) {
        const uint4* mp = (const uint4*)&g_se[j];  // 8 x u16
        uint4 m = mp[0];
        int r0 = m.x & 0xFFFF, r1 = m.x >> 16;
        int r2 = m.y & 0xFFFF, r3 = m.y >> 16;
        int r4 = m.z & 0xFFFF, r5 = m.z >> 16;
        int r6 = m.w & 0xFFFF, r7 = m.w >> 16;
        __half2 v0 = t2[r0 * 32 + lane];
        __half2 v1 = t2[r1 * 32 + lane];
        __half2 v2 = t2[r2 * 32 + lane];
        __half2 v3 = t2[r3 * 32 + lane];
        __half2 v4 = t2[r4 * 32 + lane];
        __half2 v5 = t2[r5 * 32 + lane];
        __half2 v6 = t2[r6 * 32 + lane];
        __half2 v7 = t2[r7 * 32 + lane];
        float2 f0 = __half22float2(__hadd2(v0, v1));
        float2 f1 = __half22float2(__hadd2(v2, v3));
        float2 f2 = __half22float2(__hadd2(v4, v5));
        float2 f3 = __half22float2(__hadd2(v6, v7));
        accx += f0.x + f1.x + f2.x + f3.x;
        accy += f0.y + f1.y + f2.y + f3.y;
    }

    float d = g_dinv[node];
    float2 b2 = ((const float2*)b)[lane];
    accx = b2.x + d * accx;
    accy = b2.y + d * accy;

    // layernorm over 64 features
    float ssum = accx + accy;
#pragma unroll
    for (int o = 16; o; o >>= 1) ssum += __shfl_xor_sync(0xFFFFFFFFu, ssum, o);
    float mu = ssum * (1.0f / 64.0f);
    float dx = accx - mu, dy = accy - mu;
    float var = dx * dx + dy * dy;
#pragma unroll
    for (int o = 16; o; o >>= 1) var += __shfl_xor_sync(0xFFFFFFFFu, var, o);
    float inv = rsqrtf(var * (1.0f / 64.0f) + 1e-5f);

    float2 g2 = ((const float2*)gamma)[lane];
    float2 be2 = ((const float2*)beta)[lane];
    float2* hp = (float2*)&g_h[node * H];
    float2 hres = hp[lane];
    float r0 = fmaxf(dx * inv * g2.x + be2.x, 0.0f) + hres.x;
    float r1 = fmaxf(dy * inv * g2.y + be2.y, 0.0f) + hres.y;
    hp[lane] = make_float2(r0, r1);
    ((__half2*)&g_hh[node * H])[lane] = __floats2half2_rn(r0, r1);

    if (last) {
        float2 w2 = ((const float2*)Wout)[lane];
        float o_ = r0 * w2.x + r1 * w2.y;
#pragma unroll
        for (int o = 16; o; o >>= 1) o_ += __shfl_xor_sync(0xFFFFFFFFu, o_, o);
        if (lane == 0) out[node] = o_ + bout[0];
    }
}

// ---------------- launch ----------------

extern "C" void kernel_launch(void* const* d_in, const int* in_sizes, int n_in,
                              void* d_out, int out_size) {
    const float* x      = (const float*)d_in[0];
    const int*   ei     = (const int*)d_in[1];
    const float* W_in   = (const float*)d_in[2];
    const float* b_in   = (const float*)d_in[3];
    const float* W_conv = (const float*)d_in[4];
    const float* b_conv = (const float*)d_in[5];
    const float* gamma  = (const float*)d_in[6];
    const float* beta   = (const float*)d_in[7];
    const float* W_out  = (const float*)d_in[8];
    const float* b_out  = (const float*)d_in[9];
    float* out = (float*)d_out;

    int N = in_sizes[0] / IN_DIM;
    int E = in_sizes[1] / 2;
    int nblk_scan = (N + 1023) / 1024;

    cudaStream_t s2;
    cudaStreamCreate(&s2);
    cudaEvent_t e0, eA, e1;
    cudaEventCreate(&e0);
    cudaEventCreate(&eA);
    cudaEventCreate(&e1);

    // branch A: CSR chain (stream 0)
    void* cnt_ptr = nullptr;
    cudaGetSymbolAddress(&cnt_ptr, g_cnt);
    cudaMemsetAsync(cnt_ptr, 0, (size_t)N * sizeof(int));
    count_kernel<<<(E + 255) / 256, 256>>>(ei + E, E);
    scanA<<<nblk_scan, 1024>>>(N);

    // fork branch B: convW + in_gemm (independent of CSR)
    cudaEventRecord(e0, 0);
    cudaStreamWaitEvent(s2, e0, 0);
    convW<<<48, 256, 0, s2>>>(W_conv);
    in_gemm<<<(N + 63) / 64, 256, 0, s2>>>(x, W_in, b_in, N);

    // branch A: scanC (produces dinv + rowptr), then signal eA
    scanC<<<(N + 255) / 256, 256>>>(N);
    cudaEventRecord(eA, 0);

    // branch B: conv0 once dinv is ready — overlaps with build_kernel
    cudaStreamWaitEvent(s2, eA, 0);
    conv_mma<<<(N + 127) / 128, 256, 0, s2>>>(0, N);
    cudaEventRecord(e1, s2);

    // branch A: CSR fill
    build_kernel<<<(E + 255) / 256, 256>>>(ei, E);

    // join
    cudaStreamWaitEvent(0, e1, 0);

    for (int l = 0; l < 3; l++) {
        if (l > 0) conv_mma<<<(N + 127) / 128, 256>>>(l, N);
        gather_ln<<<(N + 7) / 8, 256>>>(b_conv + l * H, gamma + l * H, beta + l * H,
                                        W_out, b_out, out, N, l == 2);
    }

    cudaEventDestroy(e0);
    cudaEventDestroy(eA);
    cudaEventDestroy(e1);
    cudaStreamDestroy(s2);
}